// round 11
// baseline (speedup 1.0000x reference)
#include <cuda_runtime.h>
#include <cuda_bf16.h>
#include <math.h>

// BboxSemanticAtt: out[b,y,x] = sigmoid( sum_i c_i * [y1<=y<y2][x1<=x<x2] )
// preds: [B, 256, 5] f32; out: [B, 512, 512] f32.
//
// Dense-store layout: lane l owns quads [128g+4l, 128g+4l+4), g=0..3, so each
// STG.128 is a contiguous 512B warp burst. One build per 32-row block (warp 0
// corner-scatters + scans the anchor row); warps 1-7 catch up to their 4-row
// chunk via bucketed events (broadcast LDS + predicated FADD). 8 warps/block
// for occupancy (~55 warps/SM). v holds g/2 (conf pre-halved); sigmoid =
// 0.5*tanh(v)+0.5 (1 MUFU).

#define FEAT   512
#define NBOX   256
#define NWARPS 8
#define CHUNK  4
#define NTHREADS (NWARPS * 32)             // 256
#define ROWS_PER_BLOCK 32                  // 8 warps x 4 rows
#define ROW_WORDS 516                      // 512 + slot for x2=512 (+ pad)
#define EVCAP  8

__global__ __launch_bounds__(NTHREADS, 6)
void bbox_att_kernel(const float* __restrict__ preds,
                     float* __restrict__ out,
                     int blocksPerBatch)
{
    __shared__ uint2 sbox[NBOX];                     // {x1|x2<<16, y1|y2<<16}
    __shared__ float sc  [NBOX];                     // 0.5 * conf
    __shared__ float brow[ROW_WORDS];                // build row -> scanned row
    __shared__ uint2 ev  [ROWS_PER_BLOCK][EVCAP];    // per-row event buckets
    __shared__ int   evn [ROWS_PER_BLOCK];
    __shared__ unsigned rowMaskS, ovMaskS;

    const int b       = blockIdx.x / blocksPerBatch;
    const int rowBase = (blockIdx.x % blocksPerBatch) * ROWS_PER_BLOCK;
    const int tid     = threadIdx.x;
    const int warp    = tid >> 5;
    const int lane    = tid & 31;

    if (tid < ROWS_PER_BLOCK) evn[tid] = 0;
    if (tid == 0) { rowMaskS = 0u; ovMaskS = 0u; }
    __syncthreads();

    // ---- load + quantize boxes; bucket ALL in-block enter/exit events ----
    for (int i = tid; i < NBOX; i += NTHREADS) {
        const float* p = preds + ((size_t)b * NBOX + i) * 5;
        float c  = p[0];
        int x1 = min(max((int)floorf(p[1] * 512.0f), 0), FEAT);
        int y1 = min(max((int)floorf(p[2] * 512.0f), 0), FEAT);
        int x2 = min(max((int)floorf(p[3] * 512.0f), 0), FEAT);
        int y2 = min(max((int)floorf(p[4] * 512.0f), 0), FEAT);
        if (!((x2 > x1) && (y2 > y1))) { y1 = 0; y2 = 0; }   // empty y-range
        sbox[i] = make_uint2((unsigned)(x1 | (x2 << 16)),
                             (unsigned)(y1 | (y2 << 16)));
        float hc = 0.5f * c;                                  // pre-halved
        sc[i] = hc;

        unsigned xp = (unsigned)x1 | ((unsigned)x2 << 10);
        int d1 = y1 - rowBase;                                // enter
        if (d1 > 0 && d1 < ROWS_PER_BLOCK) {
            atomicOr(&rowMaskS, 1u << d1);
            int e = atomicAdd(&evn[d1], 1);
            if (e < EVCAP) ev[d1][e] = make_uint2(xp, __float_as_uint(hc));
            else           atomicOr(&ovMaskS, 1u << d1);
        }
        int d2 = y2 - rowBase;                                // exit
        if (d2 > 0 && d2 < ROWS_PER_BLOCK) {
            atomicOr(&rowMaskS, 1u << d2);
            int e = atomicAdd(&evn[d2], 1);
            if (e < EVCAP) ev[d2][e] = make_uint2(xp, __float_as_uint(-hc));
            else           atomicOr(&ovMaskS, 1u << d2);
        }
    }
    __syncthreads();
    const unsigned rowMask = rowMaskS;
    const unsigned ovMask  = ovMaskS;

    // v[4g+j] = half-sum for column (128g + 4*lane + j)
    float v[16];
    float4* brow4 = (float4*)brow;

    // ---- warp 0: build + scan the block anchor row (rowBase) ----
    if (warp == 0) {
        #pragma unroll
        for (int i = lane; i < ROW_WORDS / 4; i += 32)
            brow4[i] = make_float4(0.f, 0.f, 0.f, 0.f);
        __syncwarp();

        #pragma unroll
        for (int i = lane; i < NBOX; i += 32) {
            uint2 bx = sbox[i];
            int y1 = (int)(bx.y & 0xFFFF), y2 = (int)(bx.y >> 16);
            if (y1 <= rowBase && rowBase < y2) {
                float hc = sc[i];
                atomicAdd(&brow[(int)(bx.x & 0xFFFF)],  hc);
                atomicAdd(&brow[(int)(bx.x >> 16)],    -hc);
            }
        }
        __syncwarp();

        // quad-local scans + per-g warp scans + cross-g offsets
        float4 f[4];
        #pragma unroll
        for (int g = 0; g < 4; g++) f[g] = brow4[g * 32 + lane];
        const float* fs = (const float*)f;
        float incl[4];
        #pragma unroll
        for (int g = 0; g < 4; g++) {
            float run = 0.0f;
            #pragma unroll
            for (int j = 0; j < 4; j++) { run += fs[g * 4 + j]; v[g * 4 + j] = run; }
            incl[g] = run;
        }
        #pragma unroll
        for (int o = 1; o < 32; o <<= 1) {
            float t0 = __shfl_up_sync(0xFFFFFFFFu, incl[0], o);
            float t1 = __shfl_up_sync(0xFFFFFFFFu, incl[1], o);
            float t2 = __shfl_up_sync(0xFFFFFFFFu, incl[2], o);
            float t3 = __shfl_up_sync(0xFFFFFFFFu, incl[3], o);
            if (lane >= o) { incl[0] += t0; incl[1] += t1; incl[2] += t2; incl[3] += t3; }
        }
        float off = 0.0f;
        #pragma unroll
        for (int g = 0; g < 4; g++) {
            float e = __shfl_up_sync(0xFFFFFFFFu, incl[g], 1);
            if (lane == 0) e = 0.0f;
            float add = off + e;
            #pragma unroll
            for (int j = 0; j < 4; j++) v[g * 4 + j] += add;
            off += __shfl_sync(0xFFFFFFFFu, incl[g], 31);     // total of group g
        }

        // write scanned row back (dense STS.128, same layout)
        #pragma unroll
        for (int g = 0; g < 4; g++) brow4[g * 32 + lane] = ((float4*)v)[g];
    }
    __syncthreads();

    // ---- warps 1-7: load scanned row, catch up to own anchor via events ----
    if (warp != 0) {
        #pragma unroll
        for (int g = 0; g < 4; g++) ((float4*)v)[g] = brow4[g * 32 + lane];

        const int upto = warp * CHUNK;                 // apply offsets [1, upto]
        unsigned m = rowMask & ((2u << upto) - 2u);    // bits 1..upto
        while (m) {
            int t = __ffs(m) - 1; m &= m - 1;
            if (!((ovMask >> t) & 1u)) {
                const int n = evn[t];
                for (int k = 0; k < n; k++) {
                    uint2 e = ev[t][k];
                    int x1 = (int)(e.x & 0x3FF);
                    int x2 = (int)((e.x >> 10) & 0x3FF);
                    float c2 = __uint_as_float(e.y);
                    #pragma unroll
                    for (int g = 0; g < 4; g++) {
                        int base = g * 128 + 4 * lane;
                        int lo = max(x1 - base, 0), hi = min(x2 - base, 4);
                        if (lo < hi) {
                            #pragma unroll
                            for (int j = 0; j < 4; j++)
                                if (j >= lo && j < hi) v[g * 4 + j] += c2;
                        }
                    }
                }
            } else {                                   // rare overflow: rescan
                const int yt = rowBase + t;
                for (int i = 0; i < NBOX; i++) {
                    uint2 bx = sbox[i];
                    int y1 = (int)(bx.y & 0xFFFF), y2 = (int)(bx.y >> 16);
                    bool en = (y1 == yt), ex = (y2 == yt && y2 > y1);
                    if (en || ex) {
                        float c2 = en ? sc[i] : -sc[i];
                        int x1 = (int)(bx.x & 0xFFFF);
                        int x2 = (int)(bx.x >> 16);
                        #pragma unroll
                        for (int g = 0; g < 4; g++) {
                            int base = g * 128 + 4 * lane;
                            int lo = max(x1 - base, 0), hi = min(x2 - base, 4);
                            if (lo < hi) {
                                #pragma unroll
                                for (int j = 0; j < 4; j++)
                                    if (j >= lo && j < hi) v[g * 4 + j] += c2;
                            }
                        }
                    }
                }
            }
        }
    }

    // ---- per-row: sigmoid + DENSE store, then apply next row's events ----
    const int y0 = rowBase + warp * CHUNK;
    float4* dstRow = (float4*)(out + (((size_t)b * FEAT + y0) * FEAT));

    for (int r = 0; r < CHUNK; r++) {
        float4* dst = dstRow + (size_t)r * (FEAT / 4);
        #pragma unroll
        for (int g = 0; g < 4; g++) {
            float4 t4;
            float* tp = (float*)&t4;
            #pragma unroll
            for (int j = 0; j < 4; j++) {
                float t;
                asm("tanh.approx.f32 %0, %1;" : "=f"(t) : "f"(v[g * 4 + j]));
                tp[j] = fmaf(0.5f, t, 0.5f);
            }
            dst[g * 32 + lane] = t4;    // consecutive lanes 16B apart: dense 512B
        }

        if (r + 1 < CHUNK) {
            const int target = warp * CHUNK + r + 1;   // block-row offset
            if ((rowMask >> target) & 1u) {
                if (!((ovMask >> target) & 1u)) {
                    const int n = evn[target];
                    for (int k = 0; k < n; k++) {
                        uint2 e = ev[target][k];
                        int x1 = (int)(e.x & 0x3FF);
                        int x2 = (int)((e.x >> 10) & 0x3FF);
                        float c2 = __uint_as_float(e.y);
                        #pragma unroll
                        for (int g = 0; g < 4; g++) {
                            int base = g * 128 + 4 * lane;
                            int lo = max(x1 - base, 0), hi = min(x2 - base, 4);
                            if (lo < hi) {
                                #pragma unroll
                                for (int j = 0; j < 4; j++)
                                    if (j >= lo && j < hi) v[g * 4 + j] += c2;
                            }
                        }
                    }
                } else {                               // rare overflow: rescan
                    const int yt = y0 + r + 1;
                    for (int i = 0; i < NBOX; i++) {
                        uint2 bx = sbox[i];
                        int y1 = (int)(bx.y & 0xFFFF), y2 = (int)(bx.y >> 16);
                        bool en = (y1 == yt), ex = (y2 == yt && y2 > y1);
                        if (en || ex) {
                            float c2 = en ? sc[i] : -sc[i];
                            int x1 = (int)(bx.x & 0xFFFF);
                            int x2 = (int)(bx.x >> 16);
                            #pragma unroll
                            for (int g = 0; g < 4; g++) {
                                int base = g * 128 + 4 * lane;
                                int lo = max(x1 - base, 0), hi = min(x2 - base, 4);
                                if (lo < hi) {
                                    #pragma unroll
                                    for (int j = 0; j < 4; j++)
                                        if (j >= lo && j < hi) v[g * 4 + j] += c2;
                                }
                            }
                        }
                    }
                }
            }
        }
    }
}

extern "C" void kernel_launch(void* const* d_in, const int* in_sizes, int n_in,
                              void* d_out, int out_size)
{
    const float* preds = (const float*)d_in[0];
    float* out = (float*)d_out;

    int B = in_sizes[0] / (NBOX * 5);               // 64 for bench shapes
    int blocksPerBatch = FEAT / ROWS_PER_BLOCK;     // 16
    dim3 grid(B * blocksPerBatch);                  // 1024
    dim3 block(NTHREADS);
    bbox_att_kernel<<<grid, block>>>(preds, out, blocksPerBatch);
}

// round 12
// speedup vs baseline: 1.0223x; 1.0223x over previous
#include <cuda_runtime.h>
#include <cuda_bf16.h>
#include <math.h>

// BboxSemanticAtt: out[b,y,x] = sigmoid( sum_i c_i * [y1<=y<y2][x1<=x<x2] )
// preds: [B, 256, 5] f32; out: [B, 512, 512] f32.
//
// Dense-store layout: lane l owns quads [128g+4l, 128g+4l+4), g=0..3; each
// STG.128 is a contiguous 512B warp burst. TWO anchor builds per 32-row
// block (warp 0 -> rowBase, warp 4 -> rowBase+16) so 8 warps x CHUNK=4 get
// high occupancy (8192 warps) while catch-up stays <=12 rows per warp (total
// catch-up slots = R10's 48/block). Bucketed events via broadcast LDS.
// v holds g/2 (conf pre-halved); sigmoid = 0.5*tanh(v)+0.5 (1 MUFU).

#define FEAT   512
#define NBOX   256
#define NWARPS 8
#define CHUNK  4
#define NTHREADS (NWARPS * 32)             // 256
#define ROWS_PER_BLOCK 32
#define SECROWS 16                         // rows per section
#define ROW_WORDS 516                      // 512 + slot for x2=512 (+ pad)
#define EVCAP  8

__global__ __launch_bounds__(NTHREADS, 6)
void bbox_att_kernel(const float* __restrict__ preds,
                     float* __restrict__ out,
                     int blocksPerBatch)
{
    __shared__ uint2 sbox[NBOX];                     // {x1|x2<<16, y1|y2<<16}
    __shared__ float sc  [NBOX];                     // 0.5 * conf
    __shared__ float brow[2][ROW_WORDS];             // per-section scanned rows
    __shared__ uint2 ev  [ROWS_PER_BLOCK][EVCAP];    // per-row event buckets
    __shared__ int   evn [ROWS_PER_BLOCK];
    __shared__ unsigned rowMaskS, ovMaskS;

    const int b       = blockIdx.x / blocksPerBatch;
    const int rowBase = (blockIdx.x % blocksPerBatch) * ROWS_PER_BLOCK;
    const int tid     = threadIdx.x;
    const int warp    = tid >> 5;
    const int lane    = tid & 31;
    const int sec     = warp >> 2;                   // 0 or 1
    const int wsec    = warp & 3;                    // warp index within section

    if (tid < ROWS_PER_BLOCK) evn[tid] = 0;
    if (tid == 0) { rowMaskS = 0u; ovMaskS = 0u; }
    __syncthreads();

    // ---- load + quantize boxes; bucket ALL in-block enter/exit events ----
    for (int i = tid; i < NBOX; i += NTHREADS) {
        const float* p = preds + ((size_t)b * NBOX + i) * 5;
        float c  = p[0];
        int x1 = min(max((int)floorf(p[1] * 512.0f), 0), FEAT);
        int y1 = min(max((int)floorf(p[2] * 512.0f), 0), FEAT);
        int x2 = min(max((int)floorf(p[3] * 512.0f), 0), FEAT);
        int y2 = min(max((int)floorf(p[4] * 512.0f), 0), FEAT);
        if (!((x2 > x1) && (y2 > y1))) { y1 = 0; y2 = 0; }   // empty y-range
        sbox[i] = make_uint2((unsigned)(x1 | (x2 << 16)),
                             (unsigned)(y1 | (y2 << 16)));
        float hc = 0.5f * c;                                  // pre-halved
        sc[i] = hc;

        unsigned xp = (unsigned)x1 | ((unsigned)x2 << 10);
        int d1 = y1 - rowBase;                                // enter
        if (d1 > 0 && d1 < ROWS_PER_BLOCK) {
            atomicOr(&rowMaskS, 1u << d1);
            int e = atomicAdd(&evn[d1], 1);
            if (e < EVCAP) ev[d1][e] = make_uint2(xp, __float_as_uint(hc));
            else           atomicOr(&ovMaskS, 1u << d1);
        }
        int d2 = y2 - rowBase;                                // exit
        if (d2 > 0 && d2 < ROWS_PER_BLOCK) {
            atomicOr(&rowMaskS, 1u << d2);
            int e = atomicAdd(&evn[d2], 1);
            if (e < EVCAP) ev[d2][e] = make_uint2(xp, __float_as_uint(-hc));
            else           atomicOr(&ovMaskS, 1u << d2);
        }
    }
    __syncthreads();
    const unsigned rowMask = rowMaskS;
    const unsigned ovMask  = ovMaskS;

    // v[4g+j] = half-sum for column (128g + 4*lane + j)
    float v[16];
    float*  mrow  = brow[sec];
    float4* mrow4 = (float4*)mrow;

    // ---- warps 0 & 4: build + scan this section's anchor row ----
    if (wsec == 0) {
        const int ya = rowBase + sec * SECROWS;
        #pragma unroll
        for (int i = lane; i < ROW_WORDS / 4; i += 32)
            mrow4[i] = make_float4(0.f, 0.f, 0.f, 0.f);
        __syncwarp();

        #pragma unroll
        for (int i = lane; i < NBOX; i += 32) {
            uint2 bx = sbox[i];
            int y1 = (int)(bx.y & 0xFFFF), y2 = (int)(bx.y >> 16);
            if (y1 <= ya && ya < y2) {
                float hc = sc[i];
                atomicAdd(&mrow[(int)(bx.x & 0xFFFF)],  hc);
                atomicAdd(&mrow[(int)(bx.x >> 16)],    -hc);
            }
        }
        __syncwarp();

        // quad-local scans + per-g warp scans + cross-g offsets
        float4 f[4];
        #pragma unroll
        for (int g = 0; g < 4; g++) f[g] = mrow4[g * 32 + lane];
        const float* fs = (const float*)f;
        float incl[4];
        #pragma unroll
        for (int g = 0; g < 4; g++) {
            float run = 0.0f;
            #pragma unroll
            for (int j = 0; j < 4; j++) { run += fs[g * 4 + j]; v[g * 4 + j] = run; }
            incl[g] = run;
        }
        #pragma unroll
        for (int o = 1; o < 32; o <<= 1) {
            float t0 = __shfl_up_sync(0xFFFFFFFFu, incl[0], o);
            float t1 = __shfl_up_sync(0xFFFFFFFFu, incl[1], o);
            float t2 = __shfl_up_sync(0xFFFFFFFFu, incl[2], o);
            float t3 = __shfl_up_sync(0xFFFFFFFFu, incl[3], o);
            if (lane >= o) { incl[0] += t0; incl[1] += t1; incl[2] += t2; incl[3] += t3; }
        }
        float off = 0.0f;
        #pragma unroll
        for (int g = 0; g < 4; g++) {
            float e = __shfl_up_sync(0xFFFFFFFFu, incl[g], 1);
            if (lane == 0) e = 0.0f;
            float add = off + e;
            #pragma unroll
            for (int j = 0; j < 4; j++) v[g * 4 + j] += add;
            off += __shfl_sync(0xFFFFFFFFu, incl[g], 31);     // total of group g
        }

        // write scanned row back (dense STS.128, same layout)
        #pragma unroll
        for (int g = 0; g < 4; g++) mrow4[g * 32 + lane] = ((float4*)v)[g];
    }
    __syncthreads();

    // ---- other warps: load section's scanned row, catch up via events ----
    if (wsec != 0) {
        #pragma unroll
        for (int g = 0; g < 4; g++) ((float4*)v)[g] = mrow4[g * 32 + lane];

        const int lo = sec * SECROWS;                  // anchor block-row
        const int hi = lo + wsec * CHUNK;              // apply bits (lo, hi]
        unsigned m = rowMask & ((2u << hi) - (2u << lo));
        while (m) {
            int t = __ffs(m) - 1; m &= m - 1;
            if (!((ovMask >> t) & 1u)) {
                const int n = evn[t];
                for (int k = 0; k < n; k++) {
                    uint2 e = ev[t][k];
                    int x1 = (int)(e.x & 0x3FF);
                    int x2 = (int)((e.x >> 10) & 0x3FF);
                    float c2 = __uint_as_float(e.y);
                    #pragma unroll
                    for (int g = 0; g < 4; g++) {
                        int base = g * 128 + 4 * lane;
                        int l0 = max(x1 - base, 0), h0 = min(x2 - base, 4);
                        if (l0 < h0) {
                            #pragma unroll
                            for (int j = 0; j < 4; j++)
                                if (j >= l0 && j < h0) v[g * 4 + j] += c2;
                        }
                    }
                }
            } else {                                   // rare overflow: rescan
                const int yt = rowBase + t;
                for (int i = 0; i < NBOX; i++) {
                    uint2 bx = sbox[i];
                    int y1 = (int)(bx.y & 0xFFFF), y2 = (int)(bx.y >> 16);
                    bool en = (y1 == yt), ex = (y2 == yt && y2 > y1);
                    if (en || ex) {
                        float c2 = en ? sc[i] : -sc[i];
                        int x1 = (int)(bx.x & 0xFFFF);
                        int x2 = (int)(bx.x >> 16);
                        #pragma unroll
                        for (int g = 0; g < 4; g++) {
                            int base = g * 128 + 4 * lane;
                            int l0 = max(x1 - base, 0), h0 = min(x2 - base, 4);
                            if (l0 < h0) {
                                #pragma unroll
                                for (int j = 0; j < 4; j++)
                                    if (j >= l0 && j < h0) v[g * 4 + j] += c2;
                            }
                        }
                    }
                }
            }
        }
    }

    // ---- per-row: sigmoid + DENSE store, then apply next row's events ----
    const int y0 = rowBase + warp * CHUNK;             // warp*CHUNK == sec*16 + wsec*4
    float4* dstRow = (float4*)(out + (((size_t)b * FEAT + y0) * FEAT));

    for (int r = 0; r < CHUNK; r++) {
        float4* dst = dstRow + (size_t)r * (FEAT / 4);
        #pragma unroll
        for (int g = 0; g < 4; g++) {
            float4 t4;
            float* tp = (float*)&t4;
            #pragma unroll
            for (int j = 0; j < 4; j++) {
                float t;
                asm("tanh.approx.f32 %0, %1;" : "=f"(t) : "f"(v[g * 4 + j]));
                tp[j] = fmaf(0.5f, t, 0.5f);
            }
            dst[g * 32 + lane] = t4;    // consecutive lanes 16B apart: dense 512B
        }

        if (r + 1 < CHUNK) {
            const int target = warp * CHUNK + r + 1;   // block-row offset
            if ((rowMask >> target) & 1u) {
                if (!((ovMask >> target) & 1u)) {
                    const int n = evn[target];
                    for (int k = 0; k < n; k++) {
                        uint2 e = ev[target][k];
                        int x1 = (int)(e.x & 0x3FF);
                        int x2 = (int)((e.x >> 10) & 0x3FF);
                        float c2 = __uint_as_float(e.y);
                        #pragma unroll
                        for (int g = 0; g < 4; g++) {
                            int base = g * 128 + 4 * lane;
                            int l0 = max(x1 - base, 0), h0 = min(x2 - base, 4);
                            if (l0 < h0) {
                                #pragma unroll
                                for (int j = 0; j < 4; j++)
                                    if (j >= l0 && j < h0) v[g * 4 + j] += c2;
                            }
                        }
                    }
                } else {                               // rare overflow: rescan
                    const int yt = y0 + r + 1;
                    for (int i = 0; i < NBOX; i++) {
                        uint2 bx = sbox[i];
                        int y1 = (int)(bx.y & 0xFFFF), y2 = (int)(bx.y >> 16);
                        bool en = (y1 == yt), ex = (y2 == yt && y2 > y1);
                        if (en || ex) {
                            float c2 = en ? sc[i] : -sc[i];
                            int x1 = (int)(bx.x & 0xFFFF);
                            int x2 = (int)(bx.x >> 16);
                            #pragma unroll
                            for (int g = 0; g < 4; g++) {
                                int base = g * 128 + 4 * lane;
                                int l0 = max(x1 - base, 0), h0 = min(x2 - base, 4);
                                if (l0 < h0) {
                                    #pragma unroll
                                    for (int j = 0; j < 4; j++)
                                        if (j >= l0 && j < h0) v[g * 4 + j] += c2;
                                }
                            }
                        }
                    }
                }
            }
        }
    }
}

extern "C" void kernel_launch(void* const* d_in, const int* in_sizes, int n_in,
                              void* d_out, int out_size)
{
    const float* preds = (const float*)d_in[0];
    float* out = (float*)d_out;

    int B = in_sizes[0] / (NBOX * 5);               // 64 for bench shapes
    int blocksPerBatch = FEAT / ROWS_PER_BLOCK;     // 16
    dim3 grid(B * blocksPerBatch);                  // 1024
    dim3 block(NTHREADS);
    bbox_att_kernel<<<grid, block>>>(preds, out, blocksPerBatch);
}

// round 13
// speedup vs baseline: 1.1870x; 1.1611x over previous
#include <cuda_runtime.h>
#include <cuda_bf16.h>
#include <math.h>

// BboxSemanticAtt: out[b,y,x] = sigmoid( sum_i c_i * [y1<=y<y2][x1<=x<x2] )
// preds: [B, 256, 5] f32; out: [B, 512, 512] f32.
//
// R10 config (1024 blocks x 128 thr, CHUNK=8, dense transposed stores) with
// PER-WARP independent anchor builds: each warp corner-scatters + scans its
// own anchor row (parallel, balanced) -- no catch-up chain, no post-build
// __syncthreads. Events (bucketed, broadcast LDS) only for intra-chunk rows
// (offset & 7 != 0); next-row event loads hoisted above the MUFU/STG block.
// Dense layout: lane l owns quads [128g+4l,128g+4l+4); STG.128 = 512B burst.
// v holds g/2 (conf pre-halved); sigmoid = 0.5*tanh(v)+0.5 (1 MUFU).

#define FEAT   512
#define NBOX   256
#define NWARPS 4
#define CHUNK  8
#define NTHREADS (NWARPS * 32)             // 128
#define ROWS_PER_BLOCK 32                  // 4 warps x 8 rows
#define ROW_WORDS 516                      // 512 + slot for x2=512 (+ pad)
#define EVCAP  8

__global__ __launch_bounds__(NTHREADS, 12)
void bbox_att_kernel(const float* __restrict__ preds,
                     float* __restrict__ out,
                     int blocksPerBatch)
{
    __shared__ uint2 sbox[NBOX];                     // {x1|x2<<16, y1|y2<<16}
    __shared__ float sc  [NBOX];                     // 0.5 * conf
    __shared__ float brow[NWARPS][ROW_WORDS];        // per-warp build rows
    __shared__ uint2 ev  [ROWS_PER_BLOCK][EVCAP];    // per-row event buckets
    __shared__ int   evn [ROWS_PER_BLOCK];
    __shared__ unsigned rowMaskS, ovMaskS;

    const int b       = blockIdx.x / blocksPerBatch;
    const int rowBase = (blockIdx.x % blocksPerBatch) * ROWS_PER_BLOCK;
    const int tid     = threadIdx.x;
    const int warp    = tid >> 5;
    const int lane    = tid & 31;

    if (tid < ROWS_PER_BLOCK) evn[tid] = 0;
    if (tid == 0) { rowMaskS = 0u; ovMaskS = 0u; }
    __syncthreads();

    // ---- load + quantize boxes; bucket intra-chunk enter/exit events ----
    for (int i = tid; i < NBOX; i += NTHREADS) {
        const float* p = preds + ((size_t)b * NBOX + i) * 5;
        float c  = p[0];
        int x1 = min(max((int)floorf(p[1] * 512.0f), 0), FEAT);
        int y1 = min(max((int)floorf(p[2] * 512.0f), 0), FEAT);
        int x2 = min(max((int)floorf(p[3] * 512.0f), 0), FEAT);
        int y2 = min(max((int)floorf(p[4] * 512.0f), 0), FEAT);
        if (!((x2 > x1) && (y2 > y1))) { y1 = 0; y2 = 0; }   // empty y-range
        sbox[i] = make_uint2((unsigned)(x1 | (x2 << 16)),
                             (unsigned)(y1 | (y2 << 16)));
        float hc = 0.5f * c;                                  // pre-halved
        sc[i] = hc;

        unsigned xp = (unsigned)x1 | ((unsigned)x2 << 10);
        int d1 = y1 - rowBase;                                // enter
        if (d1 > 0 && d1 < ROWS_PER_BLOCK && (d1 & (CHUNK - 1))) {
            atomicOr(&rowMaskS, 1u << d1);
            int e = atomicAdd(&evn[d1], 1);
            if (e < EVCAP) ev[d1][e] = make_uint2(xp, __float_as_uint(hc));
            else           atomicOr(&ovMaskS, 1u << d1);
        }
        int d2 = y2 - rowBase;                                // exit
        if (d2 > 0 && d2 < ROWS_PER_BLOCK && (d2 & (CHUNK - 1))) {
            atomicOr(&rowMaskS, 1u << d2);
            int e = atomicAdd(&evn[d2], 1);
            if (e < EVCAP) ev[d2][e] = make_uint2(xp, __float_as_uint(-hc));
            else           atomicOr(&ovMaskS, 1u << d2);
        }
    }
    __syncthreads();
    const unsigned rowMask = rowMaskS;
    const unsigned ovMask  = ovMaskS;

    // ---- every warp: build + scan its OWN anchor row (no cross-warp dep) ----
    // v[4g+j] = half-sum for column (128g + 4*lane + j)
    const int y0 = rowBase + warp * CHUNK;
    float*  mrow  = brow[warp];
    float4* mrow4 = (float4*)mrow;
    float v[16];

    {
        #pragma unroll
        for (int i = lane; i < ROW_WORDS / 4; i += 32)
            mrow4[i] = make_float4(0.f, 0.f, 0.f, 0.f);
        __syncwarp();

        #pragma unroll
        for (int i = lane; i < NBOX; i += 32) {
            uint2 bx = sbox[i];
            int y1 = (int)(bx.y & 0xFFFF), y2 = (int)(bx.y >> 16);
            if (y1 <= y0 && y0 < y2) {
                float hc = sc[i];
                atomicAdd(&mrow[(int)(bx.x & 0xFFFF)],  hc);
                atomicAdd(&mrow[(int)(bx.x >> 16)],    -hc);
            }
        }
        __syncwarp();

        // quad-local scans + per-g warp scans + cross-g offsets
        float4 f[4];
        #pragma unroll
        for (int g = 0; g < 4; g++) f[g] = mrow4[g * 32 + lane];
        const float* fs = (const float*)f;
        float incl[4];
        #pragma unroll
        for (int g = 0; g < 4; g++) {
            float run = 0.0f;
            #pragma unroll
            for (int j = 0; j < 4; j++) { run += fs[g * 4 + j]; v[g * 4 + j] = run; }
            incl[g] = run;
        }
        #pragma unroll
        for (int o = 1; o < 32; o <<= 1) {
            float t0 = __shfl_up_sync(0xFFFFFFFFu, incl[0], o);
            float t1 = __shfl_up_sync(0xFFFFFFFFu, incl[1], o);
            float t2 = __shfl_up_sync(0xFFFFFFFFu, incl[2], o);
            float t3 = __shfl_up_sync(0xFFFFFFFFu, incl[3], o);
            if (lane >= o) { incl[0] += t0; incl[1] += t1; incl[2] += t2; incl[3] += t3; }
        }
        float off = 0.0f;
        #pragma unroll
        for (int g = 0; g < 4; g++) {
            float e = __shfl_up_sync(0xFFFFFFFFu, incl[g], 1);
            if (lane == 0) e = 0.0f;
            float add = off + e;
            #pragma unroll
            for (int j = 0; j < 4; j++) v[g * 4 + j] += add;
            off += __shfl_sync(0xFFFFFFFFu, incl[g], 31);     // total of group g
        }
    }

    // ---- per-row: prefetch events, sigmoid + DENSE store, apply events ----
    float4* dstRow = (float4*)(out + (((size_t)b * FEAT + y0) * FEAT));

    for (int r = 0; r < CHUNK; r++) {
        // hoist next-row event loads above the MUFU/STG block (hide LDS lat)
        const int target = warp * CHUNK + r + 1;
        bool have = false, ovf = false;
        int n = 0;
        uint2 e0 = make_uint2(0u, 0u);
        if (r + 1 < CHUNK) {
            have = (rowMask >> target) & 1u;
            if (have) {
                ovf = (ovMask >> target) & 1u;
                n   = evn[target];
                e0  = ev[target][0];
            }
        }

        float4* dst = dstRow + (size_t)r * (FEAT / 4);
        #pragma unroll
        for (int g = 0; g < 4; g++) {
            float4 t4;
            float* tp = (float*)&t4;
            #pragma unroll
            for (int j = 0; j < 4; j++) {
                float t;
                asm("tanh.approx.f32 %0, %1;" : "=f"(t) : "f"(v[g * 4 + j]));
                tp[j] = fmaf(0.5f, t, 0.5f);
            }
            dst[g * 32 + lane] = t4;    // consecutive lanes 16B apart: dense 512B
        }

        if (have) {
            if (!ovf) {
                // fast path: prefetched first event, then rest
                for (int k = 0; k < n; k++) {
                    uint2 e = (k == 0) ? e0 : ev[target][k];
                    int x1 = (int)(e.x & 0x3FF);
                    int x2 = (int)((e.x >> 10) & 0x3FF);
                    float c2 = __uint_as_float(e.y);
                    #pragma unroll
                    for (int g = 0; g < 4; g++) {
                        int base = g * 128 + 4 * lane;
                        int l0 = max(x1 - base, 0), h0 = min(x2 - base, 4);
                        if (l0 < h0) {
                            #pragma unroll
                            for (int j = 0; j < 4; j++)
                                if (j >= l0 && j < h0) v[g * 4 + j] += c2;
                        }
                    }
                }
            } else {                                   // rare overflow: rescan
                const int yt = y0 + r + 1;
                for (int i = 0; i < NBOX; i++) {
                    uint2 bx = sbox[i];
                    int y1 = (int)(bx.y & 0xFFFF), y2 = (int)(bx.y >> 16);
                    bool en = (y1 == yt), ex = (y2 == yt && y2 > y1);
                    if (en || ex) {
                        float c2 = en ? sc[i] : -sc[i];
                        int x1 = (int)(bx.x & 0xFFFF);
                        int x2 = (int)(bx.x >> 16);
                        #pragma unroll
                        for (int g = 0; g < 4; g++) {
                            int base = g * 128 + 4 * lane;
                            int l0 = max(x1 - base, 0), h0 = min(x2 - base, 4);
                            if (l0 < h0) {
                                #pragma unroll
                                for (int j = 0; j < 4; j++)
                                    if (j >= l0 && j < h0) v[g * 4 + j] += c2;
                            }
                        }
                    }
                }
            }
        }
    }
}

extern "C" void kernel_launch(void* const* d_in, const int* in_sizes, int n_in,
                              void* d_out, int out_size)
{
    const float* preds = (const float*)d_in[0];
    float* out = (float*)d_out;

    int B = in_sizes[0] / (NBOX * 5);               // 64 for bench shapes
    int blocksPerBatch = FEAT / ROWS_PER_BLOCK;     // 16
    dim3 grid(B * blocksPerBatch);                  // 1024
    dim3 block(NTHREADS);
    bbox_att_kernel<<<grid, block>>>(preds, out, blocksPerBatch);
}